// round 6
// baseline (speedup 1.0000x reference)
#include <cuda_runtime.h>
#include <cuda_bf16.h>
#include <cstdint>
#include <cstddef>

#define B_ 256
#define D_ 256
#define T_ 512
#define H_ 512
#define G_ 2048  // 4*H

// ---------------- static device scratch (no allocation APIs allowed) ----------------
__device__ __align__(16) __nv_bfloat16 g_xT[(size_t)T_ * B_ * D_];    // 64 MB : x as [t*B+b][d] bf16
__device__ __align__(16) __nv_bfloat16 g_WihP[(size_t)G_ * D_];       // 1 MB  : W_ih, gate-permuted rows, bf16
__device__ __align__(16) __nv_bfloat16 g_WhhP[(size_t)G_ * H_];       // 2 MB  : W_hh, gate-permuted rows, bf16
__device__ __align__(16) float         g_biasP[G_];                   // b_ih+b_hh, permuted
__device__ __align__(16) float         g_xg[(size_t)T_ * B_ * G_];    // 1 GB  : input-gate preactivations fp32
__device__ __align__(16) __nv_bfloat16 g_hbuf[8 * 2 * 32 * H_];       // h double buffers per batch-group
__device__ __align__(16) float         g_part[(size_t)T_ * B_ * 128]; // 64 MB : MLP partial dots
__device__ unsigned                    g_cnt[8 * 32];                 // per-group monotonic counters

// ---------------- helpers ----------------
__device__ __forceinline__ unsigned sptr(const void* p) {
    return (unsigned)__cvta_generic_to_shared(p);
}
__device__ __forceinline__ void ldsm4(unsigned r[4], unsigned addr) {
    asm volatile("ldmatrix.sync.aligned.m8n8.x4.shared.b16 {%0,%1,%2,%3}, [%4];\n"
                 : "=r"(r[0]), "=r"(r[1]), "=r"(r[2]), "=r"(r[3]) : "r"(addr));
}
__device__ __forceinline__ void mmabf(float c[4], const unsigned a[4], unsigned b0, unsigned b1) {
    asm volatile("mma.sync.aligned.m16n8k16.row.col.f32.bf16.bf16.f32 "
                 "{%0,%1,%2,%3}, {%4,%5,%6,%7}, {%8,%9}, {%0,%1,%2,%3};\n"
                 : "+f"(c[0]), "+f"(c[1]), "+f"(c[2]), "+f"(c[3])
                 : "r"(a[0]), "r"(a[1]), "r"(a[2]), "r"(a[3]), "r"(b0), "r"(b1));
}
__device__ __forceinline__ float sigf(float x) { return 1.f / (1.f + __expf(-x)); }
__device__ __forceinline__ float tanh_(float x) {
    float xx = fmaxf(x, -15.f);               // avoid exp overflow -> NaN
    float e = __expf(-2.f * xx);
    return (1.f - e) / (1.f + e);
}

// gate-row permutation: ng = cta*128 + 4*du + g  <->  orig = g*512 + cta*32 + du
__device__ __forceinline__ int perm_orig(int ng) {
    int c = ng >> 7, rr = ng & 127, du = rr >> 2, g = rr & 3;
    return g * 512 + c * 32 + du;
}

// ---------------- init (re-run every launch: graph-replay deterministic) ----------------
__global__ void k_init() {
    int i = blockIdx.x * 256 + threadIdx.x;
    if (i < 8 * 2 * 32 * H_) g_hbuf[i] = __float2bfloat16(0.f);
    if (i < 256) g_cnt[i] = 0u;
}

// ---------------- transpose x[b][d][t] f32 -> g_xT[(t*B+b)][d] bf16 ----------------
__global__ void k_transpose(const float* __restrict__ x) {
    __shared__ float tile[32][33];
    int b = blockIdx.z, d0 = blockIdx.y * 32, t0 = blockIdx.x * 32;
    int li = threadIdx.x & 31, wi = threadIdx.x >> 5;  // 32 x 8
#pragma unroll
    for (int r = 0; r < 4; ++r)
        tile[wi + 8 * r][li] = x[((size_t)b * D_ + d0 + wi + 8 * r) * T_ + t0 + li];
    __syncthreads();
#pragma unroll
    for (int r = 0; r < 4; ++r) {
        int t = t0 + wi + 8 * r, d = d0 + li;
        g_xT[((size_t)t * B_ + b) * D_ + d] = __float2bfloat16(tile[li][wi + 8 * r]);
    }
}

// ---------------- weight/bias prep (permute rows, convert bf16) ----------------
__global__ void k_prep_wih(const float* __restrict__ w) {
    int idx = blockIdx.x * 256 + threadIdx.x;      // G_*D_ = 524288
    int ng = idx >> 8, d = idx & 255;
    g_WihP[idx] = __float2bfloat16(w[(size_t)perm_orig(ng) * D_ + d]);
}
__global__ void k_prep_whh(const float* __restrict__ w) {
    int idx = blockIdx.x * 256 + threadIdx.x;      // G_*H_ = 1048576
    int ng = idx >> 9, k = idx & 511;
    g_WhhP[idx] = __float2bfloat16(w[(size_t)perm_orig(ng) * H_ + k]);
}
__global__ void k_prep_bias(const float* __restrict__ bih, const float* __restrict__ bhh) {
    int ng = blockIdx.x * 256 + threadIdx.x;       // 2048
    int o = perm_orig(ng);
    g_biasP[ng] = bih[o] + bhh[o];
}

// ---------------- GEMM1: xg[m][ng] = xT @ WihP^T + biasP ; m = t*B + b ----------------
#define G1_SMEM (2 * 128 * 264 * 2)
__global__ void __launch_bounds__(256, 1) k_gemm1() {
    extern __shared__ char smraw[];
    __nv_bfloat16* As = (__nv_bfloat16*)smraw;              // 128 x 264 (pad 8 -> ldsm conflict-free)
    __nv_bfloat16* Bs = As + 128 * 264;                     // 128 x 264
    int tid = threadIdx.x;
    int m0 = blockIdx.x * 128;
    int n0 = blockIdx.y * 128;

    const uint4* gA = (const uint4*)g_xT;
    const uint4* gB = (const uint4*)g_WihP;
#pragma unroll
    for (int it = 0; it < 16; ++it) {
        int q = tid + it * 256;                 // 0..4095
        int row = q >> 5, col8 = (q & 31) * 8;
        *(uint4*)&As[row * 264 + col8] = gA[(size_t)(m0 + row) * 32 + (q & 31)];
        *(uint4*)&Bs[row * 264 + col8] = gB[(size_t)(n0 + row) * 32 + (q & 31)];
    }
    __syncthreads();

    int w = tid >> 5, L = tid & 31;
    int wm = w >> 1, wn = w & 1;                // 4x2 warp grid; warp tile 32m x 64n
    unsigned aAddr[2], bAddr[4];
    {
        int ar = wm * 32 + (L & 7) + ((L >> 3) & 1) * 8;
        int ac = (L >> 4) * 8;
        aAddr[0] = sptr(&As[ar * 264 + ac]);
        aAddr[1] = sptr(&As[(ar + 16) * 264 + ac]);
        int br = wn * 64 + (L & 7) + (L >> 4) * 8;
        int bc = ((L >> 3) & 1) * 8;
#pragma unroll
        for (int nt = 0; nt < 4; ++nt) bAddr[nt] = sptr(&Bs[(br + nt * 16) * 264 + bc]);
    }
    float acc[2][8][4];
#pragma unroll
    for (int a = 0; a < 2; ++a)
#pragma unroll
        for (int b = 0; b < 8; ++b)
#pragma unroll
            for (int c = 0; c < 4; ++c) acc[a][b][c] = 0.f;

#pragma unroll
    for (int k0 = 0; k0 < 256; k0 += 16) {
        unsigned a[2][4], bb[4][4];
        ldsm4(a[0], aAddr[0] + k0 * 2);
        ldsm4(a[1], aAddr[1] + k0 * 2);
#pragma unroll
        for (int nt = 0; nt < 4; ++nt) ldsm4(bb[nt], bAddr[nt] + k0 * 2);
#pragma unroll
        for (int mt = 0; mt < 2; ++mt)
#pragma unroll
            for (int nt = 0; nt < 4; ++nt) {
                mmabf(acc[mt][2 * nt], a[mt], bb[nt][0], bb[nt][1]);
                mmabf(acc[mt][2 * nt + 1], a[mt], bb[nt][2], bb[nt][3]);
            }
    }
    int r = L >> 2, c = L & 3;
#pragma unroll
    for (int mt = 0; mt < 2; ++mt)
#pragma unroll
        for (int nt = 0; nt < 8; ++nt) {
            int m = m0 + wm * 32 + mt * 16 + r;
            int ng = n0 + wn * 64 + nt * 8 + 2 * c;
            float b0 = g_biasP[ng], b1 = g_biasP[ng + 1];
            float2 v0 = make_float2(acc[mt][nt][0] + b0, acc[mt][nt][1] + b1);
            float2 v1 = make_float2(acc[mt][nt][2] + b0, acc[mt][nt][3] + b1);
            *(float2*)&g_xg[(size_t)m * G_ + ng] = v0;
            *(float2*)&g_xg[(size_t)(m + 8) * G_ + ng] = v1;
        }
}

// ---------------- persistent LSTM recurrence ----------------
// 128 CTAs = 8 batch-groups x 16 CTAs. CTA owns 32 hidden units (128 permuted gate rows).
// W_hh slice lives in SMEM for the entire kernel. h exchanged via global double buffer +
// per-group monotonic counter. Spin is bounded + nanosleep: a bug degrades to a wrong
// answer instead of a container-killing hang.
#define RC_SMEM ((128 * 520 + 32 * 520) * 2 + 32 * 132 * 4)
__global__ void __launch_bounds__(256, 1) k_recur(const float* __restrict__ Wmlp) {
    extern __shared__ char smraw[];
    __nv_bfloat16* Wt = (__nv_bfloat16*)smraw;              // 128 x 520
    __nv_bfloat16* Ht = Wt + 128 * 520;                     // 32 x 520
    float* Xg = (float*)(Ht + 32 * 520);                    // 32 x 132

    int tid = threadIdx.x;
    int cta = blockIdx.x & 15, grp = blockIdx.x >> 4;
    int w = tid >> 5, L = tid & 31, r = L >> 2, c = L & 3;

    // load W_hh slice once (stays resident all 512 steps)
    const uint4* gW = (const uint4*)g_WhhP;
#pragma unroll
    for (int it = 0; it < 32; ++it) {
        int q = tid + it * 256;                 // 0..8191
        int row = q >> 6, col8 = (q & 63) * 8;
        *(uint4*)&Wt[row * 520 + col8] = gW[(size_t)(cta * 128 + row) * 64 + (q & 63)];
    }

    unsigned aAddr0, aAddr1, bAddr;
    {
        int ar = (L & 7) + ((L >> 3) & 1) * 8;
        int ac = (L >> 4) * 8;
        aAddr0 = sptr(&Ht[ar * 520 + ac]);
        aAddr1 = sptr(&Ht[(ar + 16) * 520 + ac]);
        int br = w * 16 + (L & 7) + (L >> 4) * 8;
        int bc = ((L >> 3) & 1) * 8;
        bAddr = sptr(&Wt[br * 520 + bc]);
    }
    float wmv[2];
    wmv[0] = Wmlp[cta * 32 + w * 4 + 0 + (c >> 1)];
    wmv[1] = Wmlp[cta * 32 + w * 4 + 2 + (c >> 1)];

    float cst[2][2][2];                         // [m-tile][n8-tile][row-half]
#pragma unroll
    for (int a = 0; a < 2; ++a)
#pragma unroll
        for (int b = 0; b < 2; ++b) { cst[a][b][0] = 0.f; cst[a][b][1] = 0.f; }

    unsigned* cnt = &g_cnt[grp * 32];

    for (int s = 0; s < T_; ++s) {
        if (tid == 0 && s > 0) {
            unsigned tgt = 16u * (unsigned)s;
            // bounded spin: expected wait << 1 ms; bound ~ hundreds of ms
            for (long it = 0; it < 4000000L; ++it) {
                if (atomicAdd(cnt, 0u) >= tgt) break;
                __nanosleep(32);
            }
        }
        __syncthreads();
        __threadfence();   // acquire: make peer h writes visible

        // stage h_s and xg tile into SMEM (coalesced)
        {
            const uint4* gh = (const uint4*)g_hbuf;
            size_t hb = (size_t)((grp * 2 + (s & 1)) * 32) * 64;   // 64 uint4 per 512-wide row
#pragma unroll
            for (int it = 0; it < 8; ++it) {
                int q = tid + it * 256;          // 0..2047
                int row = q >> 6, col8 = (q & 63) * 8;
                *(uint4*)&Ht[row * 520 + col8] = gh[hb + row * 64 + (q & 63)];
            }
            const float4* gx = (const float4*)g_xg;
            size_t xb = (size_t)s * 256 + grp * 32;
#pragma unroll
            for (int it = 0; it < 4; ++it) {
                int q = tid + it * 256;          // 0..1023
                int row = q >> 5, col4 = (q & 31) * 4;
                *(float4*)&Xg[row * 132 + col4] =
                    gx[(xb + row) * (G_ / 4) + (cta * 128 + col4) / 4];
            }
        }
        __syncthreads();

        // MMA: [32 x 512] @ [128 x 512]^T
        float acc[2][2][4];
#pragma unroll
        for (int a = 0; a < 2; ++a)
#pragma unroll
            for (int b = 0; b < 2; ++b)
#pragma unroll
                for (int q = 0; q < 4; ++q) acc[a][b][q] = 0.f;
#pragma unroll 8
        for (int k0 = 0; k0 < 512; k0 += 16) {
            unsigned a0[4], a1[4], bb[4];
            ldsm4(a0, aAddr0 + k0 * 2);
            ldsm4(a1, aAddr1 + k0 * 2);
            ldsm4(bb, bAddr + k0 * 2);
            mmabf(acc[0][0], a0, bb[0], bb[1]);
            mmabf(acc[0][1], a0, bb[2], bb[3]);
            mmabf(acc[1][0], a1, bb[0], bb[1]);
            mmabf(acc[1][1], a1, bb[2], bb[3]);
        }

        // gates + state update + h/partial writes
        int par1 = (s + 1) & 1;
        __nv_bfloat16* hout = &g_hbuf[(size_t)((grp * 2 + par1) * 32) * 512];
        float pacc[2][2] = {{0.f, 0.f}, {0.f, 0.f}};
#pragma unroll
        for (int mt = 0; mt < 2; ++mt)
#pragma unroll
            for (int j = 0; j < 2; ++j) {
                int rowa = mt * 16 + r;
                int colx = w * 16 + j * 8 + 2 * c;
                float p0 = acc[mt][j][0] + Xg[rowa * 132 + colx];
                float p1 = acc[mt][j][1] + Xg[rowa * 132 + colx + 1];
                float p2 = acc[mt][j][2] + Xg[(rowa + 8) * 132 + colx];
                float p3 = acc[mt][j][3] + Xg[(rowa + 8) * 132 + colx + 1];
                float q0 = __shfl_xor_sync(0xffffffffu, p0, 1);
                float q1 = __shfl_xor_sync(0xffffffffu, p1, 1);
                float q2 = __shfl_xor_sync(0xffffffffu, p2, 1);
                float q3 = __shfl_xor_sync(0xffffffffu, p3, 1);
                if (!(c & 1)) {   // even lanes hold (i,f); partner lane held (g,o)
                    int u = cta * 32 + w * 4 + j * 2 + (c >> 1);
                    {
                        float iv = sigf(p0), fv = sigf(p1), gv = tanh_(q0), ov = sigf(q1);
                        float cn = fv * cst[mt][j][0] + iv * gv; cst[mt][j][0] = cn;
                        float h = ov * tanh_(cn);
                        hout[(size_t)rowa * 512 + u] = __float2bfloat16(h);
                        pacc[mt][0] += h * wmv[j];
                    }
                    {
                        float iv = sigf(p2), fv = sigf(p3), gv = tanh_(q2), ov = sigf(q3);
                        float cn = fv * cst[mt][j][1] + iv * gv; cst[mt][j][1] = cn;
                        float h = ov * tanh_(cn);
                        hout[(size_t)(rowa + 8) * 512 + u] = __float2bfloat16(h);
                        pacc[mt][1] += h * wmv[j];
                    }
                }
            }
        // MLP partial: reduce lanes c=0 and c=2, write per (warp, batch row)
#pragma unroll
        for (int mt = 0; mt < 2; ++mt)
#pragma unroll
            for (int hh = 0; hh < 2; ++hh) {
                float v = pacc[mt][hh] + __shfl_xor_sync(0xffffffffu, pacc[mt][hh], 2);
                if (c == 0) {
                    int row = mt * 16 + r + hh * 8;
                    g_part[((size_t)s * 256 + grp * 32 + row) * 128 + cta * 8 + w] = v;
                }
            }

        __threadfence();        // release h + partial writes
        __syncthreads();
        if (tid == 0) atomicAdd(cnt, 1u);
    }
}

// ---------------- final reduce: out[b][t] = sigmoid(sum_p part + b_mlp) ----------------
__global__ void k_outred(const float* __restrict__ bmlp, float* __restrict__ out) {
    int gw = (blockIdx.x * 256 + threadIdx.x) >> 5;   // one warp per (t,b)
    int lane = threadIdx.x & 31;
    float4 v = ((const float4*)g_part)[(size_t)gw * 32 + lane];
    float s = v.x + v.y + v.z + v.w;
#pragma unroll
    for (int o = 16; o; o >>= 1) s += __shfl_down_sync(0xffffffffu, s, o);
    if (lane == 0) {
        int t = gw >> 8, b = gw & 255;
        out[(size_t)b * T_ + t] = sigf(s + bmlp[0]);
    }
}

// ---------------- launch ----------------
extern "C" void kernel_launch(void* const* d_in, const int* in_sizes, int n_in,
                              void* d_out, int out_size) {
    (void)in_sizes; (void)n_in; (void)out_size;
    const float* x    = (const float*)d_in[0];
    const float* Wih  = (const float*)d_in[1];
    const float* Whh  = (const float*)d_in[2];
    const float* bih  = (const float*)d_in[3];
    const float* bhh  = (const float*)d_in[4];
    const float* Wmlp = (const float*)d_in[5];
    const float* bmlp = (const float*)d_in[6];
    float* out = (float*)d_out;

    cudaFuncSetAttribute(k_gemm1, cudaFuncAttributeMaxDynamicSharedMemorySize, G1_SMEM);
    cudaFuncSetAttribute(k_recur, cudaFuncAttributeMaxDynamicSharedMemorySize, RC_SMEM);

    k_init<<<1024, 256>>>();
    k_transpose<<<dim3(T_ / 32, D_ / 32, B_), 256>>>(x);
    k_prep_wih<<<G_ * D_ / 256, 256>>>(Wih);
    k_prep_whh<<<G_ * H_ / 256, 256>>>(Whh);
    k_prep_bias<<<G_ / 256, 256>>>(bih, bhh);
    k_gemm1<<<dim3((T_ * B_) / 128, G_ / 128), 256, G1_SMEM>>>();
    k_recur<<<128, 256, RC_SMEM>>>(Wmlp);
    k_outred<<<(T_ * B_) / 8, 256>>>(bmlp, out);
}